// round 3
// baseline (speedup 1.0000x reference)
#include <cuda_runtime.h>
#include <math.h>

// ---------------- problem constants ----------------
#define NN 100000
#define EE 3200000
#define HH 64
#define DD 256

// ---------------- scratch (device globals; no runtime alloc) ----------------
__device__ __align__(128) float g_xu[NN * HH];
__device__ __align__(128) float g_su[NN * HH];
__device__ __align__(128) float g_ew[EE];
__device__ __align__(128) float g_m[NN];
__device__ __align__(128) float g_denom[NN];
__device__ __align__(128) float g_agg[NN * HH];
__device__ __align__(128) float g_h1[NN * HH];
__device__ __align__(128) float g_t2[NN * DD];    // h1@Wm raw (BN fused into concat gemm)
__device__ __align__(128) float g_t3[NN * DD];    // concat@Wf raw
__device__ __align__(16) float g_C[HH * HH];
__device__ __align__(16) float g_A12[2 * HH * HH];
__device__ float g_ssum[2 * DD];                  // ping-pong stat slots
__device__ float g_ssq[2 * DD];
__device__ int g_idx64;

// ---------------- index dtype handling ----------------
__global__ void k_detect(const unsigned int* p) {
    if (threadIdx.x == 0 && blockIdx.x == 0) {
        int is64 = 1;
        for (int k = 1; k < 64; k += 2) {
            if (p[k] != 0u) { is64 = 0; break; }
        }
        g_idx64 = is64;
    }
}

__device__ __forceinline__ int load_idx(const void* p, long k) {
    if (g_idx64) return (int)(((const long long*)p)[k]);
    return ((const int*)p)[k];
}

// ---------------- init ----------------
__global__ void k_init(int n) {
    long total = (long)n * HH + 2L * n;
    long idx = (long)blockIdx.x * blockDim.x + threadIdx.x;
    if (idx >= total) return;
    long a = (long)n * HH;
    if (idx < a) {
        g_agg[idx] = 0.0f;
    } else if (idx < a + n) {
        g_denom[idx - a] = 0.0f;
    } else {
        ((unsigned int*)g_m)[idx - a - n] = 0xFF800000u;  // -inf
    }
}

__global__ void k_zstat() {
    int t = threadIdx.x;
    if (t < 2 * DD) { g_ssum[t] = 0.0f; g_ssq[t] = 0.0f; }
}

// ---------------- CRF matrix prep ----------------
__global__ void k_prep_crf(const float* __restrict__ c) {
    __shared__ __align__(16) float Maug[HH][2 * HH + 1];
    int tid = threadIdx.x;
    for (int idx = tid; idx < HH * HH; idx += 256) {
        int a = idx >> 6, b = idx & 63;
        float s = 0.0f;
        for (int k = 0; k < HH; k++) s += c[k * HH + a] * c[k * HH + b];
        g_C[idx] = s;
        Maug[a][b] = s + (a == b ? 1.0f : 0.0f);
        Maug[a][HH + b] = (a == b ? 1.0f : 0.0f);
    }
    __syncthreads();
    for (int p = 0; p < HH; p++) {
        float pinv = 1.0f / Maug[p][p];
        __syncthreads();
        if (tid < 2 * HH) Maug[p][tid] *= pinv;
        __syncthreads();
        int r = tid & 63, cs = tid >> 6;
        float f = (r != p) ? Maug[r][p] : 0.0f;
        __syncthreads();
        if (r != p) {
            #pragma unroll 8
            for (int q = 0; q < 32; q++) {
                int col = cs * 32 + q;
                Maug[r][col] -= f * Maug[p][col];
            }
        }
        __syncthreads();
    }
    for (int idx = tid; idx < HH * HH; idx += 256) {
        int a = idx >> 6, b = idx & 63;
        g_A12[idx] = Maug[a][HH + b];
    }
    __syncthreads();
    for (int idx = tid; idx < HH * HH; idx += 256) {
        int a = idx >> 6, b = idx & 63;
        float s = 0.0f;
        for (int k = 0; k < HH; k++) s += g_C[a * HH + k] * Maug[k][HH + b];
        g_A12[HH * HH + idx] = s;
    }
}

// ---------------- SGEMM: out[n,CO] = A[n,K] @ W[K,CO], 8x8 tiles, double-buffered
// CONCAT: logical A = cat(A, A2s); SCALE2: A2s rows scaled by 1/(denom+eps)
// STATS: accumulate column sum/sumsq into slot; NORM1: first-half A gets BN+leaky
template <int K, int CO, bool CONCAT, bool SCALE2, bool STATS, bool NORM1>
__global__ __launch_bounds__(CO == 64 ? 128 : 256) void k_gemm(
    const float* __restrict__ A, const float* __restrict__ A2s,
    const float* __restrict__ W, float* __restrict__ out,
    const float* __restrict__ ng, const float* __restrict__ nb,
    int n, int statslot, int normslot)
{
    constexpr int BM = 128, BK = 16;
    constexpr int BN = (CO == 64) ? 64 : 128;
    constexpr int NT = (CO == 64) ? 128 : 256;
    constexpr int APF = BM * BK / 4 / NT;     // float4s of A per thread
    constexpr int BPF = BK * BN / 4 / NT;     // float4s of B per thread
    constexpr int NITER = K / BK;

    __shared__ __align__(16) float As[2][BK][BM + 4];
    __shared__ __align__(16) float Bs[2][BK][BN];
    __shared__ float s_red[STATS ? 2 * BN : 1];
    __shared__ float s_sc[NORM1 ? K / 2 : 1];
    __shared__ float s_sh[NORM1 ? K / 2 : 1];

    int tid = threadIdx.x;
    int tx = tid % (BN / 8);
    int ty = tid / (BN / 8);
    int row0 = blockIdx.x * BM;
    int col0 = blockIdx.y * BN;

    if (NORM1) {
        // K/2 == 256, NT == 256
        if (tid < K / 2) {
            float fn = (float)n;
            float mu = g_ssum[normslot * DD + tid] / fn;
            float var = g_ssq[normslot * DD + tid] / fn - mu * mu;
            float scale = ng[tid] * rsqrtf(var + 1e-5f);
            s_sc[tid] = scale;
            s_sh[tid] = nb[tid] - mu * scale;
        }
        __syncthreads();
    }

    float4 ra[APF], rb[BPF];

    auto load_regs = [&](int k0) {
        #pragma unroll
        for (int p = 0; p < APF; p++) {
            int idx = tid + p * NT;
            int ar = idx >> 2;
            int af = idx & 3;
            int grow = row0 + ar;
            int gk = k0 + af * 4;
            const float* src = A;
            int stride = K;
            bool second = false;
            if (CONCAT) {
                stride = K / 2;
                if (gk >= K / 2) { src = A2s; gk -= K / 2; second = true; }
            }
            float4 v = make_float4(0.f, 0.f, 0.f, 0.f);
            if (grow < n) {
                v = *(const float4*)(src + (long)grow * stride + gk);
                if (SCALE2 && second) {
                    float rs = 1.0f / (g_denom[grow] + 1e-16f);
                    v.x *= rs; v.y *= rs; v.z *= rs; v.w *= rs;
                }
                if (NORM1 && !second) {
                    v.x = v.x * s_sc[gk + 0] + s_sh[gk + 0];
                    v.y = v.y * s_sc[gk + 1] + s_sh[gk + 1];
                    v.z = v.z * s_sc[gk + 2] + s_sh[gk + 2];
                    v.w = v.w * s_sc[gk + 3] + s_sh[gk + 3];
                    v.x = v.x > 0.f ? v.x : 0.01f * v.x;
                    v.y = v.y > 0.f ? v.y : 0.01f * v.y;
                    v.z = v.z > 0.f ? v.z : 0.01f * v.z;
                    v.w = v.w > 0.f ? v.w : 0.01f * v.w;
                }
            }
            ra[p] = v;
        }
        #pragma unroll
        for (int p = 0; p < BPF; p++) {
            int idx = tid + p * NT;
            int br = idx / (BN / 4);
            int bf = idx % (BN / 4);
            rb[p] = *(const float4*)(W + (long)(k0 + br) * CO + col0 + bf * 4);
        }
    };

    auto store_smem = [&](int buf) {
        #pragma unroll
        for (int p = 0; p < APF; p++) {
            int idx = tid + p * NT;
            int ar = idx >> 2;
            int af = idx & 3;
            As[buf][af * 4 + 0][ar] = ra[p].x;
            As[buf][af * 4 + 1][ar] = ra[p].y;
            As[buf][af * 4 + 2][ar] = ra[p].z;
            As[buf][af * 4 + 3][ar] = ra[p].w;
        }
        #pragma unroll
        for (int p = 0; p < BPF; p++) {
            int idx = tid + p * NT;
            int br = idx / (BN / 4);
            int bf = idx % (BN / 4);
            *(float4*)&Bs[buf][br][bf * 4] = rb[p];
        }
    };

    float acc[8][8];
    #pragma unroll
    for (int r = 0; r < 8; r++)
        #pragma unroll
        for (int cc = 0; cc < 8; cc++) acc[r][cc] = 0.0f;

    load_regs(0);
    store_smem(0);
    __syncthreads();

    #pragma unroll 1
    for (int t = 0; t < NITER; t++) {
        int buf = t & 1;
        if (t + 1 < NITER) load_regs((t + 1) * BK);
        #pragma unroll
        for (int kk = 0; kk < BK; kk++) {
            float a[8], b[8];
            *(float4*)&a[0] = *(const float4*)&As[buf][kk][ty * 8];
            *(float4*)&a[4] = *(const float4*)&As[buf][kk][ty * 8 + 4];
            *(float4*)&b[0] = *(const float4*)&Bs[buf][kk][tx * 8];
            *(float4*)&b[4] = *(const float4*)&Bs[buf][kk][tx * 8 + 4];
            #pragma unroll
            for (int r = 0; r < 8; r++)
                #pragma unroll
                for (int cc = 0; cc < 8; cc++)
                    acc[r][cc] += a[r] * b[cc];
        }
        if (t + 1 < NITER) store_smem(buf ^ 1);
        __syncthreads();
    }

    if (STATS && tid < 2 * BN) s_red[tid] = 0.0f;

    // write output
    #pragma unroll
    for (int r = 0; r < 8; r++) {
        int grow = row0 + ty * 8 + r;
        if (grow >= n) continue;
        *(float4*)(out + (long)grow * CO + col0 + tx * 8) =
            make_float4(acc[r][0], acc[r][1], acc[r][2], acc[r][3]);
        *(float4*)(out + (long)grow * CO + col0 + tx * 8 + 4) =
            make_float4(acc[r][4], acc[r][5], acc[r][6], acc[r][7]);
    }

    if (STATS) {
        __syncthreads();
        #pragma unroll
        for (int cc = 0; cc < 8; cc++) {
            float s = 0.0f, ss = 0.0f;
            #pragma unroll
            for (int r = 0; r < 8; r++) {
                float v = acc[r][cc];  // rows >= n hold exact zeros
                s += v; ss += v * v;
            }
            atomicAdd(&s_red[tx * 8 + cc], s);
            atomicAdd(&s_red[BN + tx * 8 + cc], ss);
        }
        __syncthreads();
        if (tid < BN) {
            atomicAdd(&g_ssum[statslot * DD + col0 + tid], s_red[tid]);
            atomicAdd(&g_ssq[statslot * DD + col0 + tid], s_red[BN + tid]);
        }
    }
}

// ---------------- BN normalize (+optional leaky relu) ----------------
template <int C, bool LEAKY>
__global__ void k_norm(const float* __restrict__ in, float* __restrict__ out,
                       const float* __restrict__ gamma, const float* __restrict__ beta,
                       int n, int slot)
{
    __shared__ float sc[C], sh[C];
    if (threadIdx.x < C) {
        float fn = (float)n;
        float mu = g_ssum[slot * DD + threadIdx.x] / fn;
        float var = g_ssq[slot * DD + threadIdx.x] / fn - mu * mu;
        float scale = gamma[threadIdx.x] * rsqrtf(var + 1e-5f);
        sc[threadIdx.x] = scale;
        sh[threadIdx.x] = beta[threadIdx.x] - mu * scale;
    }
    __syncthreads();
    long total4 = (long)n * C / 4;
    long idx = (long)blockIdx.x * blockDim.x + threadIdx.x;
    if (idx >= total4) return;
    float4 v = ((const float4*)in)[idx];
    int cb = (int)((idx * 4) % C);
    float r0 = v.x * sc[cb + 0] + sh[cb + 0];
    float r1 = v.y * sc[cb + 1] + sh[cb + 1];
    float r2 = v.z * sc[cb + 2] + sh[cb + 2];
    float r3 = v.w * sc[cb + 3] + sh[cb + 3];
    if (LEAKY) {
        r0 = r0 > 0.f ? r0 : 0.01f * r0;
        r1 = r1 > 0.f ? r1 : 0.01f * r1;
        r2 = r2 > 0.f ? r2 : 0.01f * r2;
        r3 = r3 > 0.f ? r3 : 0.01f * r3;
    }
    ((float4*)out)[idx] = make_float4(r0, r1, r2, r3);
}

// ---------------- edge pass 1: logits + segment max ----------------
__global__ void k_edge_logit(const void* __restrict__ eidx, long E) {
    long g = (long)blockIdx.x * blockDim.x + threadIdx.x;
    long e = g >> 3;
    int l8 = (int)(g & 7);
    if (e >= E) return;
    int i = load_idx(eidx, e);
    int j = load_idx(eidx, E + e);
    const float4* a = (const float4*)(g_su + (long)i * HH) + l8 * 2;
    const float4* b = (const float4*)(g_su + (long)j * HH) + l8 * 2;
    float4 a0 = a[0], a1 = a[1], b0 = b[0], b1 = b[1];
    float d0 = a0.x - b0.x, d1 = a0.y - b0.y, d2 = a0.z - b0.z, d3 = a0.w - b0.w;
    float d4 = a1.x - b1.x, d5 = a1.y - b1.y, d6 = a1.z - b1.z, d7 = a1.w - b1.w;
    float acc = d0 * d0 + d1 * d1 + d2 * d2 + d3 * d3
              + d4 * d4 + d5 * d5 + d6 * d6 + d7 * d7;
    unsigned int gmask = 0xFFu << (threadIdx.x & 24);
    acc += __shfl_xor_sync(gmask, acc, 1);
    acc += __shfl_xor_sync(gmask, acc, 2);
    acc += __shfl_xor_sync(gmask, acc, 4);
    if (l8 == 0) {
        float lg = -acc;
        g_ew[e] = lg;
        atomicMin((unsigned int*)&g_m[i], __float_as_uint(lg));
    }
}

// ---------------- edge pass 2 (fused): denom += ex; agg[i] += ex*xu[j]
__device__ __forceinline__ void red_add_v4(float* p, float4 v) {
    asm volatile("red.global.add.v4.f32 [%0], {%1,%2,%3,%4};"
                 :: "l"(p), "f"(v.x), "f"(v.y), "f"(v.z), "f"(v.w) : "memory");
}

__global__ void k_edge_expagg(const void* __restrict__ eidx, long E) {
    long g = (long)blockIdx.x * blockDim.x + threadIdx.x;
    long e = g >> 3;
    int l8 = (int)(g & 7);
    if (e >= E) return;
    int i = load_idx(eidx, e);
    int j = load_idx(eidx, E + e);
    float ex = expf(g_ew[e] - g_m[i]);
    if (l8 == 0) atomicAdd(&g_denom[i], ex);
    const float4* src = (const float4*)(g_xu + (long)j * HH) + l8 * 2;
    float* dst = g_agg + (long)i * HH + l8 * 8;
    float4 v0 = src[0], v1 = src[1];
    v0.x *= ex; v0.y *= ex; v0.z *= ex; v0.w *= ex;
    v1.x *= ex; v1.y *= ex; v1.z *= ex; v1.w *= ex;
    red_add_v4(dst, v0);
    red_add_v4(dst + 4, v1);
}

// ---------------- launch ----------------
extern "C" void kernel_launch(void* const* d_in, const int* in_sizes, int n_in,
                              void* d_out, int out_size) {
    const float* x   = (const float*)d_in[0];
    const float* y   = (const float*)d_in[1];
    const void*  eix = d_in[3];
    const float* Wu  = (const float*)d_in[4];
    const float* gu  = (const float*)d_in[5];
    const float* bu  = (const float*)d_in[6];
    const float* Wp  = (const float*)d_in[7];
    const float* gp  = (const float*)d_in[8];
    const float* bp  = (const float*)d_in[9];
    const float* cM  = (const float*)d_in[10];
    const float* Wm  = (const float*)d_in[11];
    const float* gm  = (const float*)d_in[12];
    const float* bm  = (const float*)d_in[13];
    const float* Wf  = (const float*)d_in[14];
    const float* gf  = (const float*)d_in[15];
    const float* bf  = (const float*)d_in[16];
    float* out = (float*)d_out;

    int n = in_sizes[0] / DD;
    long E = (long)in_sizes[3] / 2;

    float *xu, *su, *agg, *h1, *t2, *t3, *A12;
    cudaGetSymbolAddress((void**)&xu, g_xu);
    cudaGetSymbolAddress((void**)&su, g_su);
    cudaGetSymbolAddress((void**)&agg, g_agg);
    cudaGetSymbolAddress((void**)&h1, g_h1);
    cudaGetSymbolAddress((void**)&t2, g_t2);
    cudaGetSymbolAddress((void**)&t3, g_t3);
    cudaGetSymbolAddress((void**)&A12, g_A12);

    int rb = (n + 127) / 128;
    long init_total = (long)n * HH + 2L * n;
    int ib = (int)((init_total + 255) / 256);
    int eb8 = (int)((E * 8 + 255) / 256);
    int nb64 = (int)(((long)n * HH / 4 + 255) / 256);
    int nb256 = (int)(((long)n * DD / 4 + 255) / 256);

    k_detect<<<1, 32>>>((const unsigned int*)eix);
    k_init<<<ib, 256>>>(n);
    k_prep_crf<<<1, 256>>>(cM);
    k_zstat<<<1, 512>>>();

    // xu = BN(x @ Wu)   (stats fused -> slot 0)
    k_gemm<256, 64, false, false, true, false><<<rb, 128>>>(
        x, nullptr, Wu, xu, nullptr, nullptr, n, 0, 0);
    k_norm<64, false><<<nb64, 256>>>(xu, xu, gu, bu, n, 0);

    // su = BN(y @ Wp)   (stats fused -> slot 1)
    k_gemm<256, 64, false, false, true, false><<<rb, 128>>>(
        y, nullptr, Wp, su, nullptr, nullptr, n, 1, 0);
    k_norm<64, false><<<nb64, 256>>>(su, su, gp, bp, n, 1);

    // edge softmax + aggregation (agg unnormalized; scaled inside CRF gemm)
    k_edge_logit<<<eb8, 256>>>(eix, E);
    k_edge_expagg<<<eb8, 256>>>(eix, E);

    // h1 = cat(xu, agg/denom) @ [Minv ; C Minv]
    k_gemm<128, 64, true, true, false, false><<<rb, 128>>>(
        xu, agg, A12, h1, nullptr, nullptr, n, 0, 0);

    k_zstat<<<1, 512>>>();

    // t2 = h1 @ Wm (raw; stats -> slot 0)
    k_gemm<64, 256, false, false, true, false><<<dim3(rb, 2), 256>>>(
        h1, nullptr, Wm, t2, nullptr, nullptr, n, 0, 0);

    // t3 = cat(leakyBN(t2), y) @ Wf  (norm of t2 fused via slot 0; stats -> slot 1)
    k_gemm<512, 256, true, false, true, true><<<dim3(rb, 2), 256>>>(
        t2, y, Wf, t3, gm, bm, n, 1, 0);

    // out = leakyBN(t3)  (slot 1)
    k_norm<256, true><<<nb256, 256>>>(t3, out, gf, bf, n, 1);
}

// round 12
// speedup vs baseline: 1.5000x; 1.5000x over previous
#include <cuda_runtime.h>
#include <cuda_bf16.h>
#include <math.h>
#include <stdint.h>

// ---------------- problem constants ----------------
#define NN 100000
#define EE 3200000
#define HH 64
#define DD 256

// ---------------- scratch (device globals; no runtime alloc) ----------------
__device__ __align__(128) float g_xu[NN * HH];
__device__ __align__(128) float g_su[NN * HH];
__device__ __align__(128) float g_ew[EE];
__device__ __align__(128) float g_m[NN];
__device__ __align__(128) float g_denom[NN];
__device__ __align__(128) float g_agg[NN * HH];
__device__ __align__(128) float g_h1[NN * HH];
__device__ __align__(128) float g_t2[NN * DD];
__device__ __align__(128) float g_t3[NN * DD];
__device__ __align__(16) float g_C[HH * HH];
__device__ __align__(16) float g_A12[2 * HH * HH];   // [Minv ; C@Minv] (128 x 64)
__device__ float g_ssum[DD];
__device__ float g_ssq[DD];
__device__ int g_idx64;

// bf16 hi/lo transposed weights [CO, K]
__device__ __align__(128) __nv_bfloat16 g_WuhT[HH * DD], g_WulT[HH * DD];
__device__ __align__(128) __nv_bfloat16 g_WphT[HH * DD], g_WplT[HH * DD];
__device__ __align__(128) __nv_bfloat16 g_A12hT[HH * 2 * HH], g_A12lT[HH * 2 * HH];
__device__ __align__(128) __nv_bfloat16 g_WmhT[DD * HH], g_WmlT[DD * HH];
__device__ __align__(128) __nv_bfloat16 g_WfhT[DD * 2 * DD], g_WflT[DD * 2 * DD];

// ---------------- index dtype handling ----------------
__global__ void k_detect(const unsigned int* p) {
    if (threadIdx.x == 0 && blockIdx.x == 0) {
        int is64 = 1;
        for (int k = 1; k < 64; k += 2) {
            if (p[k] != 0u) { is64 = 0; break; }
        }
        g_idx64 = is64;
    }
}
__device__ __forceinline__ int load_idx(const void* p, long k) {
    if (g_idx64) return (int)(((const long long*)p)[k]);
    return ((const int*)p)[k];
}

// ---------------- init ----------------
__global__ void k_init(int n) {
    long total = (long)n * HH + 2L * n;
    long idx = (long)blockIdx.x * blockDim.x + threadIdx.x;
    if (idx >= total) return;
    long a = (long)n * HH;
    if (idx < a) {
        g_agg[idx] = 0.0f;
    } else if (idx < a + n) {
        g_denom[idx - a] = 0.0f;
    } else {
        ((unsigned int*)g_m)[idx - a - n] = 0xFF800000u;  // -inf
    }
}
__global__ void k_zstat() {
    int t = threadIdx.x;
    if (t < DD) { g_ssum[t] = 0.0f; g_ssq[t] = 0.0f; }
}

// ---------------- CRF matrix prep ----------------
__global__ void k_prep_crf(const float* __restrict__ c) {
    __shared__ __align__(16) float Maug[HH][2 * HH + 1];
    int tid = threadIdx.x;
    for (int idx = tid; idx < HH * HH; idx += 256) {
        int a = idx >> 6, b = idx & 63;
        float s = 0.0f;
        for (int k = 0; k < HH; k++) s += c[k * HH + a] * c[k * HH + b];
        g_C[idx] = s;
        Maug[a][b] = s + (a == b ? 1.0f : 0.0f);
        Maug[a][HH + b] = (a == b ? 1.0f : 0.0f);
    }
    __syncthreads();
    for (int p = 0; p < HH; p++) {
        float pinv = 1.0f / Maug[p][p];
        __syncthreads();
        if (tid < 2 * HH) Maug[p][tid] *= pinv;
        __syncthreads();
        int r = tid & 63, cs = tid >> 6;
        float f = (r != p) ? Maug[r][p] : 0.0f;
        __syncthreads();
        if (r != p) {
            #pragma unroll 8
            for (int q = 0; q < 32; q++) {
                int col = cs * 32 + q;
                Maug[r][col] -= f * Maug[p][col];
            }
        }
        __syncthreads();
    }
    for (int idx = tid; idx < HH * HH; idx += 256) {
        int a = idx >> 6, b = idx & 63;
        g_A12[idx] = Maug[a][HH + b];
    }
    __syncthreads();
    for (int idx = tid; idx < HH * HH; idx += 256) {
        int a = idx >> 6, b = idx & 63;
        float s = 0.0f;
        for (int k = 0; k < HH; k++) s += g_C[a * HH + k] * Maug[k][HH + b];
        g_A12[HH * HH + idx] = s;
    }
}

// ---------------- weight prep: W[K,CO] fp32 -> hi/lo bf16 transposed [CO,K] ----
template <int K, int CO>
__global__ void k_wprep(const float* __restrict__ W,
                        __nv_bfloat16* __restrict__ hT, __nv_bfloat16* __restrict__ lT) {
    int idx = blockIdx.x * 256 + threadIdx.x;
    if (idx >= K * CO) return;
    int co = idx / K, k = idx % K;
    float w = W[(long)k * CO + co];
    __nv_bfloat16 h = __float2bfloat16(w);
    hT[idx] = h;
    lT[idx] = __float2bfloat16(w - __bfloat162float(h));
}

// ---------------- mma.sync bf16 helper ----------------
__device__ __forceinline__ void mma16816(float* d, const uint32_t* a, const uint32_t* b) {
    asm volatile(
        "mma.sync.aligned.m16n8k16.row.col.f32.bf16.bf16.f32 "
        "{%0,%1,%2,%3}, {%4,%5,%6,%7}, {%8,%9}, {%0,%1,%2,%3};"
        : "+f"(d[0]), "+f"(d[1]), "+f"(d[2]), "+f"(d[3])
        : "r"(a[0]), "r"(a[1]), "r"(a[2]), "r"(a[3]), "r"(b[0]), "r"(b[1]));
}

// ---------------- split-bf16 tensor-core GEMM via mma.sync ----------------
// out[n,CO] = A[n,K] @ W[K,CO]; B as hi/lo bf16 transposed [CO,K].
// Block: 128 rows x 64 cols (gridDim.y covers CO/64). 256 threads = 8 warps (4x2).
// CONCAT: A = cat(A, A2s) (each K/2); SCALE2: second-half rows * 1/(denom+eps).
template <int K, int CO, bool CONCAT, bool SCALE2>
__global__ __launch_bounds__(256) void k_mm(
    const float* __restrict__ A, const float* __restrict__ A2s,
    const __nv_bfloat16* __restrict__ BhT, const __nv_bfloat16* __restrict__ BlT,
    float* __restrict__ out, int n)
{
    constexpr int LDS = 40;             // bf16 row stride (80B, 16B-aligned rows)
    constexpr int NCH = K / 32;
    __shared__ __align__(16) __nv_bfloat16 Ah[128 * LDS], Al[128 * LDS];
    __shared__ __align__(16) __nv_bfloat16 Bh[64 * LDS], Bl[64 * LDS];

    int tid = threadIdx.x;
    int wid = tid >> 5, lane = tid & 31;
    int wm = wid >> 1, wn = wid & 1;    // warp grid 4 x 2
    int g = lane >> 2, tg = lane & 3;
    int row0 = blockIdx.x * 128;
    int col0 = blockIdx.y * 64;

    float d[2][4][4];
    #pragma unroll
    for (int mt = 0; mt < 2; mt++)
        #pragma unroll
        for (int nt = 0; nt < 4; nt++)
            #pragma unroll
            for (int q = 0; q < 4; q++) d[mt][nt][q] = 0.0f;

    // per-thread load geometry
    int arow = tid >> 1;                // 0..127
    int ahalf = (tid & 1) * 16;         // 0 or 16
    int brow = tid >> 2;                // 0..63
    int bseg = (tid & 3) * 8;           // 0,8,16,24

    for (int ch = 0; ch < NCH; ch++) {
        int k0 = ch * 32;
        __syncthreads();
        // ---- A: 128 x 32 fp32 -> split bf16 ----
        {
            int grow = row0 + arow;
            int gk = k0 + ahalf;
            const float* src = A;
            int stride = K;
            bool second = false;
            if (CONCAT) {
                stride = K / 2;
                if (gk >= K / 2) { src = A2s; gk -= K / 2; second = true; }
            }
            float f[16];
            if (grow < n) {
                #pragma unroll
                for (int q4 = 0; q4 < 4; q4++) {
                    float4 v = *(const float4*)(src + (long)grow * stride + gk + q4 * 4);
                    f[q4 * 4 + 0] = v.x; f[q4 * 4 + 1] = v.y;
                    f[q4 * 4 + 2] = v.z; f[q4 * 4 + 3] = v.w;
                }
                if (SCALE2 && second) {
                    float rs = 1.0f / (g_denom[grow] + 1e-16f);
                    #pragma unroll
                    for (int q = 0; q < 16; q++) f[q] *= rs;
                }
            } else {
                #pragma unroll
                for (int q = 0; q < 16; q++) f[q] = 0.0f;
            }
            union { __nv_bfloat16 b[16]; uint4 u4[2]; } Uh, Ul;
            #pragma unroll
            for (int q = 0; q < 16; q++) {
                __nv_bfloat16 h = __float2bfloat16(f[q]);
                Uh.b[q] = h;
                Ul.b[q] = __float2bfloat16(f[q] - __bfloat162float(h));
            }
            *(uint4*)&Ah[arow * LDS + ahalf] = Uh.u4[0];
            *(uint4*)&Ah[arow * LDS + ahalf + 8] = Uh.u4[1];
            *(uint4*)&Al[arow * LDS + ahalf] = Ul.u4[0];
            *(uint4*)&Al[arow * LDS + ahalf + 8] = Ul.u4[1];
        }
        // ---- B: 64 x 32 bf16 hi/lo (already prepped, k-contiguous) ----
        {
            const __nv_bfloat16* ph = BhT + (long)(col0 + brow) * K + k0 + bseg;
            const __nv_bfloat16* pl = BlT + (long)(col0 + brow) * K + k0 + bseg;
            *(uint4*)&Bh[brow * LDS + bseg] = *(const uint4*)ph;
            *(uint4*)&Bl[brow * LDS + bseg] = *(const uint4*)pl;
        }
        __syncthreads();

        // ---- compute: 2 k-steps of 16 ----
        #pragma unroll
        for (int ks = 0; ks < 2; ks++) {
            int kc = ks * 16;
            uint32_t ah[2][4], al[2][4];
            #pragma unroll
            for (int mt = 0; mt < 2; mt++) {
                int r = wm * 32 + mt * 16 + g;
                int c = kc + 2 * tg;
                ah[mt][0] = *(const uint32_t*)&Ah[r * LDS + c];
                ah[mt][1] = *(const uint32_t*)&Ah[(r + 8) * LDS + c];
                ah[mt][2] = *(const uint32_t*)&Ah[r * LDS + c + 8];
                ah[mt][3] = *(const uint32_t*)&Ah[(r + 8) * LDS + c + 8];
                al[mt][0] = *(const uint32_t*)&Al[r * LDS + c];
                al[mt][1] = *(const uint32_t*)&Al[(r + 8) * LDS + c];
                al[mt][2] = *(const uint32_t*)&Al[r * LDS + c + 8];
                al[mt][3] = *(const uint32_t*)&Al[(r + 8) * LDS + c + 8];
            }
            #pragma unroll
            for (int nt = 0; nt < 4; nt++) {
                int nb = wn * 32 + nt * 8 + g;
                int c = kc + 2 * tg;
                uint32_t bh[2], bl[2];
                bh[0] = *(const uint32_t*)&Bh[nb * LDS + c];
                bh[1] = *(const uint32_t*)&Bh[nb * LDS + c + 8];
                bl[0] = *(const uint32_t*)&Bl[nb * LDS + c];
                bl[1] = *(const uint32_t*)&Bl[nb * LDS + c + 8];
                #pragma unroll
                for (int mt = 0; mt < 2; mt++) {
                    mma16816(d[mt][nt], ah[mt], bh);
                    mma16816(d[mt][nt], ah[mt], bl);
                    mma16816(d[mt][nt], al[mt], bh);
                }
            }
        }
    }

    // ---- epilogue ----
    #pragma unroll
    for (int mt = 0; mt < 2; mt++) {
        int r = row0 + wm * 32 + mt * 16 + g;
        #pragma unroll
        for (int nt = 0; nt < 4; nt++) {
            int c = col0 + wn * 32 + nt * 8 + 2 * tg;
            if (r < n)
                *(float2*)(out + (long)r * CO + c) = make_float2(d[mt][nt][0], d[mt][nt][1]);
            if (r + 8 < n)
                *(float2*)(out + (long)(r + 8) * CO + c) = make_float2(d[mt][nt][2], d[mt][nt][3]);
        }
    }
}

// ---------------- BN column stats ----------------
template <int C>
__global__ void k_stats(const float* __restrict__ in, int n) {
    constexpr int RL = 256 / C;
    int col = threadIdx.x % C;
    int rl = threadIdx.x / C;
    int r0 = blockIdx.x * 256;
    int rend = r0 + 256; if (rend > n) rend = n;
    float s = 0.0f, ss = 0.0f;
    for (int r = r0 + rl; r < rend; r += RL) {
        float v = in[(long)r * C + col];
        s += v; ss += v * v;
    }
    atomicAdd(&g_ssum[col], s);
    atomicAdd(&g_ssq[col], ss);
}

// ---------------- BN normalize (+optional leaky relu) ----------------
template <int C, bool LEAKY>
__global__ void k_norm(const float* __restrict__ in, float* __restrict__ out,
                       const float* __restrict__ gamma, const float* __restrict__ beta,
                       int n)
{
    __shared__ float sc[C], sh[C];
    if (threadIdx.x < C) {
        float fn = (float)n;
        float mu = g_ssum[threadIdx.x] / fn;
        float var = g_ssq[threadIdx.x] / fn - mu * mu;
        float scale = gamma[threadIdx.x] * rsqrtf(var + 1e-5f);
        sc[threadIdx.x] = scale;
        sh[threadIdx.x] = beta[threadIdx.x] - mu * scale;
    }
    __syncthreads();
    long total4 = (long)n * C / 4;
    long idx = (long)blockIdx.x * blockDim.x + threadIdx.x;
    if (idx >= total4) return;
    float4 v = ((const float4*)in)[idx];
    int cb = (int)((idx * 4) % C);
    float r0 = v.x * sc[cb + 0] + sh[cb + 0];
    float r1 = v.y * sc[cb + 1] + sh[cb + 1];
    float r2 = v.z * sc[cb + 2] + sh[cb + 2];
    float r3 = v.w * sc[cb + 3] + sh[cb + 3];
    if (LEAKY) {
        r0 = r0 > 0.f ? r0 : 0.01f * r0;
        r1 = r1 > 0.f ? r1 : 0.01f * r1;
        r2 = r2 > 0.f ? r2 : 0.01f * r2;
        r3 = r3 > 0.f ? r3 : 0.01f * r3;
    }
    ((float4*)out)[idx] = make_float4(r0, r1, r2, r3);
}

// ---------------- edge pass 1: logits + segment max ----------------
__global__ void k_edge_logit(const void* __restrict__ eidx, long E) {
    long g = (long)blockIdx.x * blockDim.x + threadIdx.x;
    long e = g >> 3;
    int l8 = (int)(g & 7);
    if (e >= E) return;
    int i = load_idx(eidx, e);
    int j = load_idx(eidx, E + e);
    const float4* a = (const float4*)(g_su + (long)i * HH) + l8 * 2;
    const float4* b = (const float4*)(g_su + (long)j * HH) + l8 * 2;
    float4 a0 = a[0], a1 = a[1], b0 = b[0], b1 = b[1];
    float d0 = a0.x - b0.x, d1 = a0.y - b0.y, d2 = a0.z - b0.z, d3 = a0.w - b0.w;
    float d4 = a1.x - b1.x, d5 = a1.y - b1.y, d6 = a1.z - b1.z, d7 = a1.w - b1.w;
    float acc = d0 * d0 + d1 * d1 + d2 * d2 + d3 * d3
              + d4 * d4 + d5 * d5 + d6 * d6 + d7 * d7;
    unsigned int gmask = 0xFFu << (threadIdx.x & 24);
    acc += __shfl_xor_sync(gmask, acc, 1);
    acc += __shfl_xor_sync(gmask, acc, 2);
    acc += __shfl_xor_sync(gmask, acc, 4);
    if (l8 == 0) {
        float lg = -acc;
        g_ew[e] = lg;
        atomicMin((unsigned int*)&g_m[i], __float_as_uint(lg));
    }
}

// ---------------- edge pass 2 (fused): denom += ex; agg[i] += ex*xu[j] ----
__device__ __forceinline__ void red_add_v4(float* p, float4 v) {
    asm volatile("red.global.add.v4.f32 [%0], {%1,%2,%3,%4};"
                 :: "l"(p), "f"(v.x), "f"(v.y), "f"(v.z), "f"(v.w) : "memory");
}
__global__ void k_edge_expagg(const void* __restrict__ eidx, long E) {
    long g = (long)blockIdx.x * blockDim.x + threadIdx.x;
    long e = g >> 3;
    int l8 = (int)(g & 7);
    if (e >= E) return;
    int i = load_idx(eidx, e);
    int j = load_idx(eidx, E + e);
    float ex = expf(g_ew[e] - g_m[i]);
    if (l8 == 0) atomicAdd(&g_denom[i], ex);
    const float4* src = (const float4*)(g_xu + (long)j * HH) + l8 * 2;
    float* dst = g_agg + (long)i * HH + l8 * 8;
    float4 v0 = src[0], v1 = src[1];
    v0.x *= ex; v0.y *= ex; v0.z *= ex; v0.w *= ex;
    v1.x *= ex; v1.y *= ex; v1.z *= ex; v1.w *= ex;
    red_add_v4(dst, v0);
    red_add_v4(dst + 4, v1);
}

// ---------------- launch ----------------
extern "C" void kernel_launch(void* const* d_in, const int* in_sizes, int n_in,
                              void* d_out, int out_size) {
    const float* x   = (const float*)d_in[0];
    const float* y   = (const float*)d_in[1];
    const void*  eix = d_in[3];
    const float* Wu  = (const float*)d_in[4];
    const float* gu  = (const float*)d_in[5];
    const float* bu  = (const float*)d_in[6];
    const float* Wp  = (const float*)d_in[7];
    const float* gp  = (const float*)d_in[8];
    const float* bp  = (const float*)d_in[9];
    const float* cM  = (const float*)d_in[10];
    const float* Wm  = (const float*)d_in[11];
    const float* gm  = (const float*)d_in[12];
    const float* bm  = (const float*)d_in[13];
    const float* Wf  = (const float*)d_in[14];
    const float* gf  = (const float*)d_in[15];
    const float* bf  = (const float*)d_in[16];
    float* out = (float*)d_out;

    int n = in_sizes[0] / DD;
    long E = (long)in_sizes[3] / 2;

    float *xu, *su, *agg, *h1, *t2, *t3, *A12;
    cudaGetSymbolAddress((void**)&xu, g_xu);
    cudaGetSymbolAddress((void**)&su, g_su);
    cudaGetSymbolAddress((void**)&agg, g_agg);
    cudaGetSymbolAddress((void**)&h1, g_h1);
    cudaGetSymbolAddress((void**)&t2, g_t2);
    cudaGetSymbolAddress((void**)&t3, g_t3);
    cudaGetSymbolAddress((void**)&A12, g_A12);
    __nv_bfloat16 *WuhT, *WulT, *WphT, *WplT, *A12hT, *A12lT, *WmhT, *WmlT, *WfhT, *WflT;
    cudaGetSymbolAddress((void**)&WuhT, g_WuhT); cudaGetSymbolAddress((void**)&WulT, g_WulT);
    cudaGetSymbolAddress((void**)&WphT, g_WphT); cudaGetSymbolAddress((void**)&WplT, g_WplT);
    cudaGetSymbolAddress((void**)&A12hT, g_A12hT); cudaGetSymbolAddress((void**)&A12lT, g_A12lT);
    cudaGetSymbolAddress((void**)&WmhT, g_WmhT); cudaGetSymbolAddress((void**)&WmlT, g_WmlT);
    cudaGetSymbolAddress((void**)&WfhT, g_WfhT); cudaGetSymbolAddress((void**)&WflT, g_WflT);

    int rb = (n + 127) / 128;
    int sb = (n + 255) / 256;
    long init_total = (long)n * HH + 2L * n;
    int ib = (int)((init_total + 255) / 256);
    int eb8 = (int)((E * 8 + 255) / 256);
    int nb64 = (int)(((long)n * HH / 4 + 255) / 256);
    int nb256 = (int)(((long)n * DD / 4 + 255) / 256);

    k_detect<<<1, 32>>>((const unsigned int*)eix);
    k_init<<<ib, 256>>>(n);
    k_prep_crf<<<1, 256>>>(cM);

    // weight prep (small)
    k_wprep<256, 64><<<(256 * 64 + 255) / 256, 256>>>(Wu, WuhT, WulT);
    k_wprep<256, 64><<<(256 * 64 + 255) / 256, 256>>>(Wp, WphT, WplT);
    k_wprep<128, 64><<<(128 * 64 + 255) / 256, 256>>>(A12, A12hT, A12lT);
    k_wprep<64, 256><<<(64 * 256 + 255) / 256, 256>>>(Wm, WmhT, WmlT);
    k_wprep<512, 256><<<(512 * 256 + 255) / 256, 256>>>(Wf, WfhT, WflT);

    // xu = BN(x @ Wu)
    k_mm<256, 64, false, false><<<rb, 256>>>(x, nullptr, WuhT, WulT, xu, n);
    k_zstat<<<1, 256>>>();
    k_stats<64><<<sb, 256>>>(xu, n);
    k_norm<64, false><<<nb64, 256>>>(xu, xu, gu, bu, n);

    // su = BN(y @ Wp)
    k_mm<256, 64, false, false><<<rb, 256>>>(y, nullptr, WphT, WplT, su, n);
    k_zstat<<<1, 256>>>();
    k_stats<64><<<sb, 256>>>(su, n);
    k_norm<64, false><<<nb64, 256>>>(su, su, gp, bp, n);

    // edge softmax + aggregation (agg unnormalized; scaled inside CRF gemm)
    k_edge_logit<<<eb8, 256>>>(eix, E);
    k_edge_expagg<<<eb8, 256>>>(eix, E);

    // h1 = cat(xu, agg/denom) @ [Minv ; C Minv]
    k_mm<128, 64, true, true><<<rb, 256>>>(xu, agg, A12hT, A12lT, h1, n);

    // t2 = h1 @ Wm ; h2 = leakyBN(t2) in place
    k_mm<64, 256, false, false><<<dim3(rb, 4), 256>>>(h1, nullptr, WmhT, WmlT, t2, n);
    k_zstat<<<1, 256>>>();
    k_stats<256><<<sb, 256>>>(t2, n);
    k_norm<256, true><<<nb256, 256>>>(t2, t2, gm, bm, n);

    // t3 = cat(h2, y) @ Wf ; out = leakyBN(t3)
    k_mm<512, 256, true, false><<<dim3(rb, 4), 256>>>(t2, y, WfhT, WflT, t3, n);
    k_zstat<<<1, 256>>>();
    k_stats<256><<<sb, 256>>>(t3, n);
    k_norm<256, true><<<nb256, 256>>>(t3, out, gf, bf, n);
}

// round 16
// speedup vs baseline: 1.5164x; 1.0109x over previous
#include <cuda_runtime.h>
#include <cuda_bf16.h>
#include <math.h>
#include <stdint.h>

// ---------------- problem constants ----------------
#define NN 100000
#define EE 3200000
#define HH 64
#define DD 256

// ---------------- scratch (device globals; no runtime alloc) ----------------
__device__ __align__(128) float g_xu[NN * HH];
__device__ __align__(128) float g_su[NN * HH];
__device__ __align__(128) float g_ew[EE];
__device__ __align__(128) float g_m[NN];
__device__ __align__(128) float g_denom[NN];
__device__ __align__(128) float g_agg[NN * HH];
__device__ __align__(128) float g_h1[NN * HH];
__device__ __align__(128) float g_t2[NN * DD];
__device__ __align__(128) float g_t3[NN * DD];
__device__ __align__(16) float g_C[HH * HH];
__device__ __align__(16) float g_A12[2 * HH * HH];   // [Minv ; C@Minv] (128 x 64)
__device__ float g_ssum[DD];
__device__ float g_ssq[DD];
__device__ int g_idx64;

// bf16 hi/lo transposed weights [CO, K]
__device__ __align__(128) __nv_bfloat16 g_WuhT[HH * DD], g_WulT[HH * DD];
__device__ __align__(128) __nv_bfloat16 g_WphT[HH * DD], g_WplT[HH * DD];
__device__ __align__(128) __nv_bfloat16 g_A12hT[HH * 2 * HH], g_A12lT[HH * 2 * HH];
__device__ __align__(128) __nv_bfloat16 g_WmhT[DD * HH], g_WmlT[DD * HH];
__device__ __align__(128) __nv_bfloat16 g_WfhT[DD * 2 * DD], g_WflT[DD * 2 * DD];

// ---------------- index dtype handling ----------------
__global__ void k_detect(const unsigned int* p) {
    if (threadIdx.x == 0 && blockIdx.x == 0) {
        int is64 = 1;
        for (int k = 1; k < 64; k += 2) {
            if (p[k] != 0u) { is64 = 0; break; }
        }
        g_idx64 = is64;
    }
}
__device__ __forceinline__ int load_idx(const void* p, long k) {
    if (g_idx64) return (int)(((const long long*)p)[k]);
    return ((const int*)p)[k];
}

// ---------------- init ----------------
__global__ void k_init(int n) {
    long total = (long)n * HH + 2L * n;
    long idx = (long)blockIdx.x * blockDim.x + threadIdx.x;
    if (idx >= total) return;
    long a = (long)n * HH;
    if (idx < a) {
        g_agg[idx] = 0.0f;
    } else if (idx < a + n) {
        g_denom[idx - a] = 0.0f;
    } else {
        ((unsigned int*)g_m)[idx - a - n] = 0xFF800000u;  // -inf
    }
}
__global__ void k_zstat() {
    int t = threadIdx.x;
    if (t < DD) { g_ssum[t] = 0.0f; g_ssq[t] = 0.0f; }
}

// ---------------- CRF matrix prep ----------------
__global__ void k_prep_crf(const float* __restrict__ c) {
    __shared__ __align__(16) float Maug[HH][2 * HH + 1];
    int tid = threadIdx.x;
    for (int idx = tid; idx < HH * HH; idx += 256) {
        int a = idx >> 6, b = idx & 63;
        float s = 0.0f;
        for (int k = 0; k < HH; k++) s += c[k * HH + a] * c[k * HH + b];
        g_C[idx] = s;
        Maug[a][b] = s + (a == b ? 1.0f : 0.0f);
        Maug[a][HH + b] = (a == b ? 1.0f : 0.0f);
    }
    __syncthreads();
    for (int p = 0; p < HH; p++) {
        float pinv = 1.0f / Maug[p][p];
        __syncthreads();
        if (tid < 2 * HH) Maug[p][tid] *= pinv;
        __syncthreads();
        int r = tid & 63, cs = tid >> 6;
        float f = (r != p) ? Maug[r][p] : 0.0f;
        __syncthreads();
        if (r != p) {
            #pragma unroll 8
            for (int q = 0; q < 32; q++) {
                int col = cs * 32 + q;
                Maug[r][col] -= f * Maug[p][col];
            }
        }
        __syncthreads();
    }
    for (int idx = tid; idx < HH * HH; idx += 256) {
        int a = idx >> 6, b = idx & 63;
        g_A12[idx] = Maug[a][HH + b];
    }
    __syncthreads();
    for (int idx = tid; idx < HH * HH; idx += 256) {
        int a = idx >> 6, b = idx & 63;
        float s = 0.0f;
        for (int k = 0; k < HH; k++) s += g_C[a * HH + k] * Maug[k][HH + b];
        g_A12[HH * HH + idx] = s;
    }
}

// ---------------- weight prep: W[K,CO] fp32 -> hi/lo bf16 transposed [CO,K] ----
template <int K, int CO>
__global__ void k_wprep(const float* __restrict__ W,
                        __nv_bfloat16* __restrict__ hT, __nv_bfloat16* __restrict__ lT) {
    int idx = blockIdx.x * 256 + threadIdx.x;
    if (idx >= K * CO) return;
    int co = idx / K, k = idx % K;
    float w = W[(long)k * CO + co];
    __nv_bfloat16 h = __float2bfloat16(w);
    hT[idx] = h;
    lT[idx] = __float2bfloat16(w - __bfloat162float(h));
}

// ---------------- mma.sync + ldmatrix helpers ----------------
__device__ __forceinline__ void mma16816(float* d, const uint32_t* a, const uint32_t* b) {
    asm volatile(
        "mma.sync.aligned.m16n8k16.row.col.f32.bf16.bf16.f32 "
        "{%0,%1,%2,%3}, {%4,%5,%6,%7}, {%8,%9}, {%0,%1,%2,%3};"
        : "+f"(d[0]), "+f"(d[1]), "+f"(d[2]), "+f"(d[3])
        : "r"(a[0]), "r"(a[1]), "r"(a[2]), "r"(a[3]), "r"(b[0]), "r"(b[1]));
}
__device__ __forceinline__ void ldmx4(uint32_t* r, const void* p) {
    uint32_t addr = (uint32_t)__cvta_generic_to_shared(p);
    asm volatile("ldmatrix.sync.aligned.m8n8.x4.shared.b16 {%0,%1,%2,%3}, [%4];"
                 : "=r"(r[0]), "=r"(r[1]), "=r"(r[2]), "=r"(r[3]) : "r"(addr));
}

// ---------------- split-bf16 tensor-core GEMM via mma.sync + ldmatrix ----------
// out[n,CO] = A[n,K] @ W[K,CO]; B as hi/lo bf16 transposed [CO,K].
// Block: 128 rows x 64 cols (gridDim.y covers CO/64). 256 threads = 8 warps (4x2).
// CONCAT: A = cat(A, A2s) (each K/2); SCALE2: second-half rows * 1/(denom+eps).
template <int K, int CO, bool CONCAT, bool SCALE2>
__global__ __launch_bounds__(256) void k_mm(
    const float* __restrict__ A, const float* __restrict__ A2s,
    const __nv_bfloat16* __restrict__ BhT, const __nv_bfloat16* __restrict__ BlT,
    float* __restrict__ out, int n)
{
    constexpr int LDS = 40;             // bf16 row stride (80B, 16B-aligned rows)
    constexpr int NCH = K / 32;
    __shared__ __align__(16) __nv_bfloat16 Ah[128 * LDS], Al[128 * LDS];
    __shared__ __align__(16) __nv_bfloat16 Bh[64 * LDS], Bl[64 * LDS];

    int tid = threadIdx.x;
    int wid = tid >> 5, lane = tid & 31;
    int wm = wid >> 1, wn = wid & 1;    // warp grid 4 x 2
    int g = lane >> 2, tg = lane & 3;
    int row0 = blockIdx.x * 128;
    int col0 = blockIdx.y * 64;

    // ldmatrix per-thread row/col select (8x8 quads)
    int quad = lane >> 3, tr = lane & 7;
    int rsel = (quad & 1) * 8 + tr;
    int csel = (quad >> 1) * 8;

    float d[2][4][4];
    #pragma unroll
    for (int mt = 0; mt < 2; mt++)
        #pragma unroll
        for (int nt = 0; nt < 4; nt++)
            #pragma unroll
            for (int q = 0; q < 4; q++) d[mt][nt][q] = 0.0f;

    // per-thread load geometry
    int arow = tid >> 1;                // 0..127
    int ahalf = (tid & 1) * 16;         // 0 or 16
    int brow = tid >> 2;                // 0..63
    int bseg = (tid & 3) * 8;           // 0,8,16,24

    for (int ch = 0; ch < NCH; ch++) {
        int k0 = ch * 32;
        __syncthreads();
        // ---- A: 128 x 32 fp32 -> split bf16 ----
        {
            int grow = row0 + arow;
            int gk = k0 + ahalf;
            const float* src = A;
            int stride = K;
            bool second = false;
            if (CONCAT) {
                stride = K / 2;
                if (gk >= K / 2) { src = A2s; gk -= K / 2; second = true; }
            }
            float f[16];
            if (grow < n) {
                #pragma unroll
                for (int q4 = 0; q4 < 4; q4++) {
                    float4 v = *(const float4*)(src + (long)grow * stride + gk + q4 * 4);
                    f[q4 * 4 + 0] = v.x; f[q4 * 4 + 1] = v.y;
                    f[q4 * 4 + 2] = v.z; f[q4 * 4 + 3] = v.w;
                }
                if (SCALE2 && second) {
                    float rs = 1.0f / (g_denom[grow] + 1e-16f);
                    #pragma unroll
                    for (int q = 0; q < 16; q++) f[q] *= rs;
                }
            } else {
                #pragma unroll
                for (int q = 0; q < 16; q++) f[q] = 0.0f;
            }
            union { __nv_bfloat16 b[16]; uint4 u4[2]; } Uh, Ul;
            #pragma unroll
            for (int q = 0; q < 16; q++) {
                __nv_bfloat16 h = __float2bfloat16(f[q]);
                Uh.b[q] = h;
                Ul.b[q] = __float2bfloat16(f[q] - __bfloat162float(h));
            }
            *(uint4*)&Ah[arow * LDS + ahalf] = Uh.u4[0];
            *(uint4*)&Ah[arow * LDS + ahalf + 8] = Uh.u4[1];
            *(uint4*)&Al[arow * LDS + ahalf] = Ul.u4[0];
            *(uint4*)&Al[arow * LDS + ahalf + 8] = Ul.u4[1];
        }
        // ---- B: 64 x 32 bf16 hi/lo (already prepped, k-contiguous) ----
        {
            const __nv_bfloat16* ph = BhT + (long)(col0 + brow) * K + k0 + bseg;
            const __nv_bfloat16* pl = BlT + (long)(col0 + brow) * K + k0 + bseg;
            *(uint4*)&Bh[brow * LDS + bseg] = *(const uint4*)ph;
            *(uint4*)&Bl[brow * LDS + bseg] = *(const uint4*)pl;
        }
        __syncthreads();

        // ---- compute: 2 k-steps of 16, fragments via ldmatrix.x4 ----
        #pragma unroll
        for (int ks = 0; ks < 2; ks++) {
            int kc = ks * 16;
            uint32_t ah[2][4], al[2][4];
            #pragma unroll
            for (int mt = 0; mt < 2; mt++) {
                ldmx4(ah[mt], &Ah[(wm * 32 + mt * 16 + rsel) * LDS + kc + csel]);
                ldmx4(al[mt], &Al[(wm * 32 + mt * 16 + rsel) * LDS + kc + csel]);
            }
            uint32_t bh[2][4], bl[2][4];
            #pragma unroll
            for (int gq = 0; gq < 2; gq++) {
                ldmx4(bh[gq], &Bh[(wn * 32 + gq * 16 + rsel) * LDS + kc + csel]);
                ldmx4(bl[gq], &Bl[(wn * 32 + gq * 16 + rsel) * LDS + kc + csel]);
            }
            #pragma unroll
            for (int nt = 0; nt < 4; nt++) {
                int gq = nt >> 1, hf = nt & 1;
                uint32_t bfh[2] = { bh[gq][hf], bh[gq][2 + hf] };
                uint32_t bfl[2] = { bl[gq][hf], bl[gq][2 + hf] };
                #pragma unroll
                for (int mt = 0; mt < 2; mt++) {
                    mma16816(d[mt][nt], ah[mt], bfh);
                    mma16816(d[mt][nt], ah[mt], bfl);
                    mma16816(d[mt][nt], al[mt], bfh);
                }
            }
        }
    }

    // ---- epilogue ----
    #pragma unroll
    for (int mt = 0; mt < 2; mt++) {
        int r = row0 + wm * 32 + mt * 16 + g;
        #pragma unroll
        for (int nt = 0; nt < 4; nt++) {
            int c = col0 + wn * 32 + nt * 8 + 2 * tg;
            if (r < n)
                *(float2*)(out + (long)r * CO + c) = make_float2(d[mt][nt][0], d[mt][nt][1]);
            if (r + 8 < n)
                *(float2*)(out + (long)(r + 8) * CO + c) = make_float2(d[mt][nt][2], d[mt][nt][3]);
        }
    }
}

// ---------------- BN column stats ----------------
template <int C>
__global__ void k_stats(const float* __restrict__ in, int n) {
    constexpr int RL = 256 / C;
    int col = threadIdx.x % C;
    int rl = threadIdx.x / C;
    int r0 = blockIdx.x * 256;
    int rend = r0 + 256; if (rend > n) rend = n;
    float s = 0.0f, ss = 0.0f;
    for (int r = r0 + rl; r < rend; r += RL) {
        float v = in[(long)r * C + col];
        s += v; ss += v * v;
    }
    atomicAdd(&g_ssum[col], s);
    atomicAdd(&g_ssq[col], ss);
}

// ---------------- BN normalize (+optional leaky relu) ----------------
template <int C, bool LEAKY>
__global__ void k_norm(const float* __restrict__ in, float* __restrict__ out,
                       const float* __restrict__ gamma, const float* __restrict__ beta,
                       int n)
{
    __shared__ float sc[C], sh[C];
    if (threadIdx.x < C) {
        float fn = (float)n;
        float mu = g_ssum[threadIdx.x] / fn;
        float var = g_ssq[threadIdx.x] / fn - mu * mu;
        float scale = gamma[threadIdx.x] * rsqrtf(var + 1e-5f);
        sc[threadIdx.x] = scale;
        sh[threadIdx.x] = beta[threadIdx.x] - mu * scale;
    }
    __syncthreads();
    long total4 = (long)n * C / 4;
    long idx = (long)blockIdx.x * blockDim.x + threadIdx.x;
    if (idx >= total4) return;
    float4 v = ((const float4*)in)[idx];
    int cb = (int)((idx * 4) % C);
    float r0 = v.x * sc[cb + 0] + sh[cb + 0];
    float r1 = v.y * sc[cb + 1] + sh[cb + 1];
    float r2 = v.z * sc[cb + 2] + sh[cb + 2];
    float r3 = v.w * sc[cb + 3] + sh[cb + 3];
    if (LEAKY) {
        r0 = r0 > 0.f ? r0 : 0.01f * r0;
        r1 = r1 > 0.f ? r1 : 0.01f * r1;
        r2 = r2 > 0.f ? r2 : 0.01f * r2;
        r3 = r3 > 0.f ? r3 : 0.01f * r3;
    }
    ((float4*)out)[idx] = make_float4(r0, r1, r2, r3);
}

// ---------------- edge pass 1: logits + segment max ----------------
__global__ void k_edge_logit(const void* __restrict__ eidx, long E) {
    long g = (long)blockIdx.x * blockDim.x + threadIdx.x;
    long e = g >> 3;
    int l8 = (int)(g & 7);
    if (e >= E) return;
    int i = load_idx(eidx, e);
    int j = load_idx(eidx, E + e);
    const float4* a = (const float4*)(g_su + (long)i * HH) + l8 * 2;
    const float4* b = (const float4*)(g_su + (long)j * HH) + l8 * 2;
    float4 a0 = a[0], a1 = a[1], b0 = b[0], b1 = b[1];
    float d0 = a0.x - b0.x, d1 = a0.y - b0.y, d2 = a0.z - b0.z, d3 = a0.w - b0.w;
    float d4 = a1.x - b1.x, d5 = a1.y - b1.y, d6 = a1.z - b1.z, d7 = a1.w - b1.w;
    float acc = d0 * d0 + d1 * d1 + d2 * d2 + d3 * d3
              + d4 * d4 + d5 * d5 + d6 * d6 + d7 * d7;
    unsigned int gmask = 0xFFu << (threadIdx.x & 24);
    acc += __shfl_xor_sync(gmask, acc, 1);
    acc += __shfl_xor_sync(gmask, acc, 2);
    acc += __shfl_xor_sync(gmask, acc, 4);
    if (l8 == 0) {
        float lg = -acc;
        g_ew[e] = lg;
        atomicMin((unsigned int*)&g_m[i], __float_as_uint(lg));
    }
}

// ---------------- edge pass 2 (fused): denom += ex; agg[i] += ex*xu[j] ----
__device__ __forceinline__ void red_add_v4(float* p, float4 v) {
    asm volatile("red.global.add.v4.f32 [%0], {%1,%2,%3,%4};"
                 :: "l"(p), "f"(v.x), "f"(v.y), "f"(v.z), "f"(v.w) : "memory");
}
__global__ void k_edge_expagg(const void* __restrict__ eidx, long E) {
    long g = (long)blockIdx.x * blockDim.x + threadIdx.x;
    long e = g >> 3;
    int l8 = (int)(g & 7);
    if (e >= E) return;
    int i = load_idx(eidx, e);
    int j = load_idx(eidx, E + e);
    float ex = expf(g_ew[e] - g_m[i]);
    if (l8 == 0) atomicAdd(&g_denom[i], ex);
    const float4* src = (const float4*)(g_xu + (long)j * HH) + l8 * 2;
    float* dst = g_agg + (long)i * HH + l8 * 8;
    float4 v0 = src[0], v1 = src[1];
    v0.x *= ex; v0.y *= ex; v0.z *= ex; v0.w *= ex;
    v1.x *= ex; v1.y *= ex; v1.z *= ex; v1.w *= ex;
    red_add_v4(dst, v0);
    red_add_v4(dst + 4, v1);
}

// ---------------- launch ----------------
extern "C" void kernel_launch(void* const* d_in, const int* in_sizes, int n_in,
                              void* d_out, int out_size) {
    const float* x   = (const float*)d_in[0];
    const float* y   = (const float*)d_in[1];
    const void*  eix = d_in[3];
    const float* Wu  = (const float*)d_in[4];
    const float* gu  = (const float*)d_in[5];
    const float* bu  = (const float*)d_in[6];
    const float* Wp  = (const float*)d_in[7];
    const float* gp  = (const float*)d_in[8];
    const float* bp  = (const float*)d_in[9];
    const float* cM  = (const float*)d_in[10];
    const float* Wm  = (const float*)d_in[11];
    const float* gm  = (const float*)d_in[12];
    const float* bm  = (const float*)d_in[13];
    const float* Wf  = (const float*)d_in[14];
    const float* gf  = (const float*)d_in[15];
    const float* bf  = (const float*)d_in[16];
    float* out = (float*)d_out;

    int n = in_sizes[0] / DD;
    long E = (long)in_sizes[3] / 2;

    float *xu, *su, *agg, *h1, *t2, *t3, *A12;
    cudaGetSymbolAddress((void**)&xu, g_xu);
    cudaGetSymbolAddress((void**)&su, g_su);
    cudaGetSymbolAddress((void**)&agg, g_agg);
    cudaGetSymbolAddress((void**)&h1, g_h1);
    cudaGetSymbolAddress((void**)&t2, g_t2);
    cudaGetSymbolAddress((void**)&t3, g_t3);
    cudaGetSymbolAddress((void**)&A12, g_A12);
    __nv_bfloat16 *WuhT, *WulT, *WphT, *WplT, *A12hT, *A12lT, *WmhT, *WmlT, *WfhT, *WflT;
    cudaGetSymbolAddress((void**)&WuhT, g_WuhT); cudaGetSymbolAddress((void**)&WulT, g_WulT);
    cudaGetSymbolAddress((void**)&WphT, g_WphT); cudaGetSymbolAddress((void**)&WplT, g_WplT);
    cudaGetSymbolAddress((void**)&A12hT, g_A12hT); cudaGetSymbolAddress((void**)&A12lT, g_A12lT);
    cudaGetSymbolAddress((void**)&WmhT, g_WmhT); cudaGetSymbolAddress((void**)&WmlT, g_WmlT);
    cudaGetSymbolAddress((void**)&WfhT, g_WfhT); cudaGetSymbolAddress((void**)&WflT, g_WflT);

    int rb = (n + 127) / 128;
    int sb = (n + 255) / 256;
    long init_total = (long)n * HH + 2L * n;
    int ib = (int)((init_total + 255) / 256);
    int eb8 = (int)((E * 8 + 255) / 256);
    int nb64 = (int)(((long)n * HH / 4 + 255) / 256);
    int nb256 = (int)(((long)n * DD / 4 + 255) / 256);

    k_detect<<<1, 32>>>((const unsigned int*)eix);
    k_init<<<ib, 256>>>(n);
    k_prep_crf<<<1, 256>>>(cM);

    // weight prep (small)
    k_wprep<256, 64><<<(256 * 64 + 255) / 256, 256>>>(Wu, WuhT, WulT);
    k_wprep<256, 64><<<(256 * 64 + 255) / 256, 256>>>(Wp, WphT, WplT);
    k_wprep<128, 64><<<(128 * 64 + 255) / 256, 256>>>(A12, A12hT, A12lT);
    k_wprep<64, 256><<<(64 * 256 + 255) / 256, 256>>>(Wm, WmhT, WmlT);
    k_wprep<512, 256><<<(512 * 256 + 255) / 256, 256>>>(Wf, WfhT, WflT);

    // xu = BN(x @ Wu)
    k_mm<256, 64, false, false><<<rb, 256>>>(x, nullptr, WuhT, WulT, xu, n);
    k_zstat<<<1, 256>>>();
    k_stats<64><<<sb, 256>>>(xu, n);
    k_norm<64, false><<<nb64, 256>>>(xu, xu, gu, bu, n);

    // su = BN(y @ Wp)
    k_mm<256, 64, false, false><<<rb, 256>>>(y, nullptr, WphT, WplT, su, n);
    k_zstat<<<1, 256>>>();
    k_stats<64><<<sb, 256>>>(su, n);
    k_norm<64, false><<<nb64, 256>>>(su, su, gp, bp, n);

    // edge softmax + aggregation (agg unnormalized; scaled inside CRF gemm)
    k_edge_logit<<<eb8, 256>>>(eix, E);
    k_edge_expagg<<<eb8, 256>>>(eix, E);

    // h1 = cat(xu, agg/denom) @ [Minv ; C Minv]
    k_mm<128, 64, true, true><<<rb, 256>>>(xu, agg, A12hT, A12lT, h1, n);

    // t2 = h1 @ Wm ; h2 = leakyBN(t2) in place
    k_mm<64, 256, false, false><<<dim3(rb, 4), 256>>>(h1, nullptr, WmhT, WmlT, t2, n);
    k_zstat<<<1, 256>>>();
    k_stats<256><<<sb, 256>>>(t2, n);
    k_norm<256, true><<<nb256, 256>>>(t2, t2, gm, bm, n);

    // t3 = cat(h2, y) @ Wf ; out = leakyBN(t3)
    k_mm<512, 256, true, false><<<dim3(rb, 4), 256>>>(t2, y, WfhT, WflT, t3, n);
    k_zstat<<<1, 256>>>();
    k_stats<256><<<sb, 256>>>(t3, n);
    k_norm<256, true><<<nb256, 256>>>(t3, out, gf, bf, n);
}